// round 9
// baseline (speedup 1.0000x reference)
#include <cuda_runtime.h>
#include <cstdint>

#define BB 16
#define TT 1024
#define SS 256
#define CC 256
#define LN_EPS 1e-3f

#define TTILE 16   // t's per block in k2
#define TG 4       // t-group for register blocking

// ---------------- scratch (device globals; no allocations) ----------------
__device__ float g_part[BB * 8 * SS * 16];  // conv partial sums
__device__ float g_cw[BB * SS * 16];        // layer-1 constant vector, w path
__device__ float g_ca[BB * SS * 16];        // layer-1 constant vector, a path
__device__ uint2 g_ctxS[BB * SS * CC];      // tf32 (hi,lo) split of ctx
__device__ uint2 g_wpaS[272 * CC];          // tf32 (hi,lo) split of w_pa

// sm_100a lessons (measured):
//  - tanh.approx.f32 silu: +600us (R4, sw-emulated). BANNED.
//  - fma.rn.f32x2 inline asm: catastrophic slowdown (R5). BANNED.
__device__ __forceinline__ float silu_f(float x) {
    float e = __expf(-x);
    return __fdividef(x, 1.0f + e);
}

// ---- TF32 helpers (3xTF32 split for fp32-grade tensor-core GEMM) ----
__device__ __forceinline__ uint32_t tf32_of(float x) {
    uint32_t r; asm("cvt.rna.tf32.f32 %0, %1;" : "=r"(r) : "f"(x)); return r;
}
__device__ __forceinline__ void tf32_split(float x, uint32_t& hi, uint32_t& lo) {
    hi = tf32_of(x);
    lo = tf32_of(x - __uint_as_float(hi));
}
__device__ __forceinline__ void mma_tf32(
    float& d0, float& d1, float& d2, float& d3,
    uint32_t a0, uint32_t a1, uint32_t a2, uint32_t a3,
    uint32_t b0, uint32_t b1)
{
    asm volatile(
        "mma.sync.aligned.m16n8k8.row.col.f32.tf32.tf32.f32 "
        "{%0,%1,%2,%3}, {%4,%5,%6,%7}, {%8,%9}, {%0,%1,%2,%3};"
        : "+f"(d0), "+f"(d1), "+f"(d2), "+f"(d3)
        : "r"(a0), "r"(a1), "r"(a2), "r"(a3), "r"(b0), "r"(b1));
}

// ================= K1a: conv partials over 32-channel chunks =================
__global__ __launch_bounds__(256) void k1a_conv(
    const float* __restrict__ ctx,
    const float* __restrict__ wcw,
    const float* __restrict__ wca)
{
    __shared__ float s_ctx[SS * 33];
    __shared__ float s_w[2][3 * 32 * 8];

    int b = blockIdx.x >> 3;
    int chunk = blockIdx.x & 7;
    int c0 = chunk * 32;
    int tid = threadIdx.x;

    for (int i = tid; i < SS * 32; i += 256) {
        int row = i >> 5, c = i & 31;
        s_ctx[row * 33 + c] = ctx[((size_t)b * SS + row) * CC + c0 + c];
    }
    for (int i = tid; i < 3 * 32 * 8; i += 256) {
        int k = i / 256, rem = i % 256;
        s_w[0][i] = wcw[(size_t)k * CC * 8 + (size_t)c0 * 8 + rem];
        s_w[1][i] = wca[(size_t)k * CC * 8 + (size_t)c0 * 8 + rem];
    }
    __syncthreads();

    int s = tid;
    float hw[8], ha[8];
    #pragma unroll
    for (int cc = 0; cc < 8; cc++) { hw[cc] = 0.f; ha[cc] = 0.f; }

    #pragma unroll
    for (int k = 0; k < 3; k++) {
        int row = s + k - 1;
        if (row < 0 || row >= SS) continue;
        for (int c = 0; c < 32; c++) {
            float v = s_ctx[row * 33 + c];
            #pragma unroll
            for (int cc = 0; cc < 8; cc++) {
                hw[cc] = fmaf(v, s_w[0][(k * 32 + c) * 8 + cc], hw[cc]);
                ha[cc] = fmaf(v, s_w[1][(k * 32 + c) * 8 + cc], ha[cc]);
            }
        }
    }
    float* dst = &g_part[(((size_t)b * 8 + chunk) * SS + s) * 16];
    #pragma unroll
    for (int cc = 0; cc < 8; cc++) { dst[cc] = hw[cc]; dst[8 + cc] = ha[cc]; }
}

// ========== K1b: cumsum + reduce partials + LN + silu + c-vectors ==========
__global__ __launch_bounds__(256) void k1b_setup(
    const float* __restrict__ dur,
    const float* __restrict__ bcw, const float* __restrict__ glnw,
    const float* __restrict__ blnw, const float* __restrict__ w1w,
    const float* __restrict__ b1w,
    const float* __restrict__ bca, const float* __restrict__ glna,
    const float* __restrict__ blna, const float* __restrict__ w1a,
    const float* __restrict__ b1a)
{
    __shared__ float s_scan[SS];
    int b = blockIdx.x, s = threadIdx.x;

    float d = dur[(size_t)b * SS + s];
    s_scan[s] = d;
    __syncthreads();
    for (int off = 1; off < SS; off <<= 1) {
        float v = (s >= off) ? s_scan[s - off] : 0.f;
        __syncthreads();
        s_scan[s] += v;
        __syncthreads();
    }
    float e0 = s_scan[s];
    float s0 = e0 - d;

    float h[16];
    #pragma unroll
    for (int p = 0; p < 16; p++) h[p] = 0.f;
    for (int ch = 0; ch < 8; ch++) {
        const float* src = &g_part[(((size_t)b * 8 + ch) * SS + s) * 16];
        #pragma unroll
        for (int p = 0; p < 16; p++) h[p] += src[p];
    }

    for (int p = 0; p < 2; p++) {
        const float* bconv = (p == 0) ? bcw : bca;
        const float* gln   = (p == 0) ? glnw : glna;
        const float* bln   = (p == 0) ? blnw : blna;
        const float* w1    = (p == 0) ? w1w : w1a;
        const float* b1    = (p == 0) ? b1w : b1a;
        float* dst         = (p == 0) ? g_cw : g_ca;

        float hv[8];
        float mu = 0.f;
        #pragma unroll
        for (int cc = 0; cc < 8; cc++) {
            hv[cc] = h[p * 8 + cc] + bconv[cc];
            mu += hv[cc];
        }
        mu *= 0.125f;
        float var = 0.f;
        #pragma unroll
        for (int cc = 0; cc < 8; cc++) {
            float dd = hv[cc] - mu;
            var += dd * dd;
        }
        var *= 0.125f;
        float inv = rsqrtf(var + LN_EPS);
        float hs[8];
        #pragma unroll
        for (int cc = 0; cc < 8; cc++)
            hs[cc] = silu_f((hv[cc] - mu) * inv * gln[cc] + bln[cc]);

        #pragma unroll
        for (int j = 0; j < 16; j++) {
            float val = b1[j] - s0 * w1[8 * 16 + j] + (e0 + s0) * w1[9 * 16 + j];
            #pragma unroll
            for (int cc = 0; cc < 8; cc++)
                val = fmaf(hs[cc], w1[cc * 16 + j], val);
            dst[((size_t)b * SS + s) * 16 + j] = val;
        }
    }
}

// ========== K1c: precompute tf32 splits of ctx and w_pa (hoisted cvt) ==========
__global__ __launch_bounds__(256) void k1c_split(
    const float* __restrict__ ctx, const float* __restrict__ wpa)
{
    int i = blockIdx.x * 256 + threadIdx.x;
    if (i < BB * SS * CC) {
        uint32_t h, l; tf32_split(ctx[i], h, l);
        g_ctxS[i] = make_uint2(h, l);
    }
    if (i < 272 * CC) {
        uint32_t h, l; tf32_split(wpa[i], h, l);
        g_wpaS[i] = make_uint2(h, l);
    }
}

// ===================== K2: fused main kernel =====================
// grid = (T/TTILE, B), 256 threads
// smem floats:
//   s_cw     [0,     4352)  256*17  (aliased by s_concat stride 276 after 1c)
//   s_ca     [4352,  8704)  256*17
//   s_wt     [8704, 12800)  [t][256]            (dead after 1c; aliased by u_cat_lo in phase 3)
//   s_w2w    [12800,13056)                      (dead after 1a)
//   s_w2a    [13056,13312)                      (dead after 1c)
//   s_small  [13312,13408)
//   s_part   [13408,15456)  16*8*16
//   s_wtF_hi [15456,19552)  tf32 A-frag of w (hi)   (dead after phase 2; aliased by u_cat_hi)
//   s_wtF_lo [19552,23648)  tf32 A-frag of w (lo)
//   u_cat_hi = sm+15456 (4416 u32), u_cat_lo = sm+8704 (4416 u32)  [phase 3 only]
#define K2_SMEM_FLOATS 23648
#define K2_SMEM_BYTES (K2_SMEM_FLOATS * 4)

__global__ __launch_bounds__(256, 2) void k2_main(
    const float* __restrict__ ctx, const float* __restrict__ mask,
    const float* __restrict__ w1w, const float* __restrict__ w2w,
    const float* __restrict__ b2w, const float* __restrict__ wpw,
    const float* __restrict__ bpw,
    const float* __restrict__ w1a, const float* __restrict__ w2a,
    const float* __restrict__ b2a,
    const float* __restrict__ wpa, const float* __restrict__ bpa,
    float* __restrict__ out)
{
    extern __shared__ float sm[];
    float* s_cw     = sm;
    float* s_ca     = sm + 4352;
    float* s_wt     = sm + 8704;
    float* s_w2w    = sm + 12800;
    float* s_w2a    = sm + 13056;
    float* s_small  = sm + 13312;
    float* s_part   = sm + 13408;
    uint32_t* u_wtF_hi = (uint32_t*)(sm + 15456);
    uint32_t* u_wtF_lo = (uint32_t*)(sm + 19552);
    float* s_concat = s_cw;  // alias; live only after phase 1c (stride 276)
    uint32_t* u_cat_hi = (uint32_t*)(sm + 15456);  // phase-3 alias (wtF dead)
    uint32_t* u_cat_lo = (uint32_t*)(sm + 8704);   // phase-3 alias (s_wt/w2 dead)

    int tid = threadIdx.x;
    int lane = tid & 31, wid = tid >> 5;
    int b = blockIdx.y;
    int t0 = blockIdx.x * TTILE;

    // ---- load weights ----
    s_w2w[tid] = w2w[tid];
    s_w2a[tid] = w2a[tid];
    if (tid < 16) {
        s_small[tid]      = w1w[128 + tid] - w1w[144 + tid];  // dw
        s_small[16 + tid] = w1a[128 + tid] - w1a[144 + tid];  // da
        s_small[32 + tid] = wpw[tid];
        s_small[48 + tid] = b2w[tid];
        s_small[64 + tid] = b2a[tid];
    }
    {
        const float4* cw4 = (const float4*)&g_cw[((size_t)b * SS + tid) * 16];
        const float4* ca4 = (const float4*)&g_ca[((size_t)b * SS + tid) * 16];
        #pragma unroll
        for (int q = 0; q < 4; q++) {
            float4 v = cw4[q];
            s_cw[tid * 17 + q * 4 + 0] = v.x; s_cw[tid * 17 + q * 4 + 1] = v.y;
            s_cw[tid * 17 + q * 4 + 2] = v.z; s_cw[tid * 17 + q * 4 + 3] = v.w;
            float4 w = ca4[q];
            s_ca[tid * 17 + q * 4 + 0] = w.x; s_ca[tid * 17 + q * 4 + 1] = w.y;
            s_ca[tid * 17 + q * 4 + 2] = w.z; s_ca[tid * 17 + q * 4 + 3] = w.w;
        }
    }
    float bp0 = bpw[0];
    __syncthreads();

    // ---- Phase 1a: logits for all TTILE t's ----
    for (int g = 0; g < TTILE / TG; g++) {
        float y[TG][16];
        #pragma unroll
        for (int u = 0; u < TG; u++)
            #pragma unroll
            for (int i = 0; i < 16; i++) y[u][i] = s_small[48 + i];

        for (int j = 0; j < 16; j++) {
            float cv = s_cw[tid * 17 + j];
            float dv = s_small[j];
            float xj[TG];
            #pragma unroll
            for (int u = 0; u < TG; u++)
                xj[u] = silu_f(fmaf((float)(t0 + g * TG + u), dv, cv));
            #pragma unroll
            for (int i = 0; i < 16; i++) {
                float w = s_w2w[j * 16 + i];
                #pragma unroll
                for (int u = 0; u < TG; u++)
                    y[u][i] = fmaf(xj[u], w, y[u][i]);
            }
        }
        #pragma unroll
        for (int u = 0; u < TG; u++) {
            float lg = bp0;
            #pragma unroll
            for (int i = 0; i < 16; i++)
                lg = fmaf(silu_f(y[u][i]), s_small[32 + i], lg);
            s_wt[(g * TG + u) * SS + tid] = lg;
        }
    }
    __syncthreads();

    // ---- Phase 1b: warp-private masked softmax; also emit tf32 A-fragments ----
    {
        const float* mask0 = mask + (size_t)b * TT * SS;
        #pragma unroll
        for (int tt = 0; tt < 2; tt++) {
            int t = wid * 2 + tt;
            float lg[8];
            #pragma unroll
            for (int k = 0; k < 8; k++) {
                int s = lane + 32 * k;
                float m0 = mask0[s];
                lg[k] = fmaf(m0, s_wt[t * SS + s], (1.0f - m0) * -1000000.0f);
            }
            float mx = lg[0];
            #pragma unroll
            for (int k = 1; k < 8; k++) mx = fmaxf(mx, lg[k]);
            #pragma unroll
            for (int off = 16; off > 0; off >>= 1)
                mx = fmaxf(mx, __shfl_xor_sync(0xffffffffu, mx, off));
            float p[8], sum = 0.f;
            #pragma unroll
            for (int k = 0; k < 8; k++) { p[k] = __expf(lg[k] - mx); sum += p[k]; }
            #pragma unroll
            for (int off = 16; off > 0; off >>= 1)
                sum += __shfl_xor_sync(0xffffffffu, sum, off);
            float inv = __fdividef(1.0f, sum);
            const float* mrow = mask + ((size_t)b * TT + t0 + t) * SS;
            float* orow = out + ((size_t)b * TT + t0 + t) * SS;
            #pragma unroll
            for (int k = 0; k < 8; k++) {
                int s = lane + 32 * k;
                float wv = p[k] * inv * mrow[s];
                s_wt[t * SS + s] = wv;
                orow[s] = wv;
                uint32_t hi, lo;
                tf32_split(wv, hi, lo);
                int ks = s >> 3;
                int lf = ((t & 7) << 2) | (s & 3);
                int rg = (t >> 3) | (((s >> 2) & 1) << 1);
                int fi = ks * 128 + lf * 4 + rg;
                u_wtF_hi[fi] = hi;
                u_wtF_lo[fi] = lo;
            }
        }
    }
    __syncthreads();

    // ---- Phase 1c: a-path MLP, weighted + warp-reduced ----
    for (int g = 0; g < TTILE / TG; g++) {
        float y[TG][16];
        #pragma unroll
        for (int u = 0; u < TG; u++)
            #pragma unroll
            for (int i = 0; i < 16; i++) y[u][i] = s_small[64 + i];

        for (int j = 0; j < 16; j++) {
            float cv = s_ca[tid * 17 + j];
            float dv = s_small[16 + j];
            float xj[TG];
            #pragma unroll
            for (int u = 0; u < TG; u++)
                xj[u] = silu_f(fmaf((float)(t0 + g * TG + u), dv, cv));
            #pragma unroll
            for (int i = 0; i < 16; i++) {
                float w = s_w2a[j * 16 + i];
                #pragma unroll
                for (int u = 0; u < TG; u++)
                    y[u][i] = fmaf(xj[u], w, y[u][i]);
            }
        }
        #pragma unroll
        for (int u = 0; u < TG; u++) {
            float wv = s_wt[(g * TG + u) * SS + tid];
            #pragma unroll
            for (int i = 0; i < 16; i++)
                y[u][i] = silu_f(y[u][i]) * wv;
        }
        #pragma unroll
        for (int off = 16; off > 0; off >>= 1)
            #pragma unroll
            for (int u = 0; u < TG; u++)
                #pragma unroll
                for (int i = 0; i < 16; i++)
                    y[u][i] += __shfl_xor_sync(0xffffffffu, y[u][i], off);
        if (lane == 0) {
            #pragma unroll
            for (int u = 0; u < TG; u++)
                #pragma unroll
                for (int i = 0; i < 16; i++)
                    s_part[((g * TG + u) * 8 + wid) * 16 + i] = y[u][i];
        }
    }
    __syncthreads();

    // ---- Phase 1d: finish aux reduction -> s_concat[t][256+m] (stride 276) ----
    {
        int t = tid >> 4, m = tid & 15;
        float a = 0.f;
        #pragma unroll
        for (int w8 = 0; w8 < 8; w8++)
            a += s_part[(t * 8 + w8) * 16 + m];
        s_concat[t * 276 + 256 + m] = a;
    }

    // ---- Phase 2 (tensor cores, 3xTF32; B pre-split in gmem) ----
    {
        int n_base = wid * 32;
        float acc[4][4];
        #pragma unroll
        for (int nt = 0; nt < 4; nt++)
            #pragma unroll
            for (int q = 0; q < 4; q++) acc[nt][q] = 0.f;

        const uint2* bS = g_ctxS + (size_t)b * SS * CC + (lane & 3) * CC + (lane >> 2);
        #pragma unroll 4
        for (int ks = 0; ks < 32; ks++) {
            uint4 ah = *(const uint4*)&u_wtF_hi[ks * 128 + lane * 4];
            uint4 al = *(const uint4*)&u_wtF_lo[ks * 128 + lane * 4];
            const uint2* bk = bS + ks * 8 * CC;
            #pragma unroll
            for (int nt = 0; nt < 4; nt++) {
                int n0 = n_base + nt * 8;
                uint2 b0 = bk[n0];
                uint2 b1 = bk[4 * CC + n0];
                mma_tf32(acc[nt][0], acc[nt][1], acc[nt][2], acc[nt][3],
                         ah.x, ah.y, ah.z, ah.w, b0.x, b1.x);
                mma_tf32(acc[nt][0], acc[nt][1], acc[nt][2], acc[nt][3],
                         ah.x, ah.y, ah.z, ah.w, b0.y, b1.y);
                mma_tf32(acc[nt][0], acc[nt][1], acc[nt][2], acc[nt][3],
                         al.x, al.y, al.z, al.w, b0.x, b1.x);
            }
        }
        int r0 = lane >> 2, c2 = 2 * (lane & 3);
        #pragma unroll
        for (int nt = 0; nt < 4; nt++) {
            int c = n_base + nt * 8 + c2;
            *(float2*)&s_concat[r0 * 276 + c]       = make_float2(acc[nt][0], acc[nt][1]);
            *(float2*)&s_concat[(r0 + 8) * 276 + c] = make_float2(acc[nt][2], acc[nt][3]);
        }
    }
    __syncthreads();

    // ---- Phase 3 prelude: split s_concat ONCE into smem hi/lo (frag A source) ----
    {
        #pragma unroll
        for (int q = 0; q < 17; q++) {
            int idx = q * 256 + tid;         // 0..4351
            int t = idx / 272, k = idx - t * 272;
            float v = s_concat[t * 276 + k];
            uint32_t hi, lo;
            tf32_split(v, hi, lo);
            u_cat_hi[t * 276 + k] = hi;
            u_cat_lo[t * 276 + k] = lo;
        }
    }
    __syncthreads();

    // ---- Phase 3 (tensor cores, 3xTF32; A pre-split smem, B pre-split gmem) ----
    {
        int n_base = wid * 32;
        float acc[4][4];
        #pragma unroll
        for (int nt = 0; nt < 4; nt++)
            #pragma unroll
            for (int q = 0; q < 4; q++) acc[nt][q] = 0.f;

        int ab = (lane >> 2) * 276 + (lane & 3);
        const uint2* wS = g_wpaS + (lane & 3) * CC + (lane >> 2);
        #pragma unroll 2
        for (int ks = 0; ks < 34; ks++) {
            uint32_t ah0 = u_cat_hi[ab + ks * 8];
            uint32_t ah1 = u_cat_hi[ab + 8 * 276 + ks * 8];
            uint32_t ah2 = u_cat_hi[ab + ks * 8 + 4];
            uint32_t ah3 = u_cat_hi[ab + 8 * 276 + ks * 8 + 4];
            uint32_t al0 = u_cat_lo[ab + ks * 8];
            uint32_t al1 = u_cat_lo[ab + 8 * 276 + ks * 8];
            uint32_t al2 = u_cat_lo[ab + ks * 8 + 4];
            uint32_t al3 = u_cat_lo[ab + 8 * 276 + ks * 8 + 4];
            const uint2* wk = wS + ks * 8 * CC;
            #pragma unroll
            for (int nt = 0; nt < 4; nt++) {
                int n0 = n_base + nt * 8;
                uint2 w0 = wk[n0];
                uint2 w1 = wk[4 * CC + n0];
                mma_tf32(acc[nt][0], acc[nt][1], acc[nt][2], acc[nt][3],
                         ah0, ah1, ah2, ah3, w0.x, w1.x);
                mma_tf32(acc[nt][0], acc[nt][1], acc[nt][2], acc[nt][3],
                         ah0, ah1, ah2, ah3, w0.y, w1.y);
                mma_tf32(acc[nt][0], acc[nt][1], acc[nt][2], acc[nt][3],
                         al0, al1, al2, al3, w0.x, w1.x);
            }
        }
        int r0 = lane >> 2, c2 = 2 * (lane & 3);
        float* oal = out + (size_t)BB * TT * SS;
        #pragma unroll
        for (int nt = 0; nt < 4; nt++) {
            int c = n_base + nt * 8 + c2;
            float2 bias = *(const float2*)&bpa[c];
            size_t o0 = ((size_t)b * TT + t0 + r0) * CC + c;
            size_t o1 = ((size_t)b * TT + t0 + r0 + 8) * CC + c;
            *(float2*)&oal[o0] = make_float2(acc[nt][0] + bias.x, acc[nt][1] + bias.y);
            *(float2*)&oal[o1] = make_float2(acc[nt][2] + bias.x, acc[nt][3] + bias.y);
        }
    }
}

// ============================ launch ============================
extern "C" void kernel_launch(void* const* d_in, const int* in_sizes, int n_in,
                              void* d_out, int out_size) {
    (void)in_sizes; (void)n_in; (void)out_size;
    const float* ctx  = (const float*)d_in[0];
    const float* dur  = (const float*)d_in[1];
    const float* mask = (const float*)d_in[2];
    const float* wcw  = (const float*)d_in[3];
    const float* bcw  = (const float*)d_in[4];
    const float* glnw = (const float*)d_in[5];
    const float* blnw = (const float*)d_in[6];
    const float* w1w  = (const float*)d_in[7];
    const float* b1w  = (const float*)d_in[8];
    const float* w2w  = (const float*)d_in[9];
    const float* b2w  = (const float*)d_in[10];
    const float* wpw  = (const float*)d_in[11];
    const float* bpw  = (const float*)d_in[12];
    const float* wca  = (const float*)d_in[13];
    const float* bca  = (const float*)d_in[14];
    const float* glna = (const float*)d_in[15];
    const float* blna = (const float*)d_in[16];
    const float* w1a  = (const float*)d_in[17];
    const float* b1a  = (const float*)d_in[18];
    const float* w2a  = (const float*)d_in[19];
    const float* b2a  = (const float*)d_in[20];
    const float* wpa  = (const float*)d_in[21];
    const float* bpa  = (const float*)d_in[22];
    float* out = (float*)d_out;

    k1a_conv<<<BB * 8, 256>>>(ctx, wcw, wca);
    k1c_split<<<(BB * SS * CC + 255) / 256, 256>>>(ctx, wpa);
    k1b_setup<<<BB, 256>>>(dur, bcw, glnw, blnw, w1w, b1w,
                           bca, glna, blna, w1a, b1a);

    cudaFuncSetAttribute(k2_main, cudaFuncAttributeMaxDynamicSharedMemorySize,
                         K2_SMEM_BYTES);
    dim3 grid(TT / TTILE, BB);
    k2_main<<<grid, 256, K2_SMEM_BYTES>>>(
        ctx, mask, w1w, w2w, b2w, wpw, bpw,
        w1a, w2a, b2a, wpa, bpa, out);
}